// round 15
// baseline (speedup 1.0000x reference)
#include <cuda_runtime.h>
#include <cuda_fp16.h>
#include <cstdint>

// ---------------------------------------------------------------------------
// Problem constants
// ---------------------------------------------------------------------------
#define B_   8
#define C_   256
#define N_   4096
#define G_   8
#define CPG_ 32
#define EPS_ 1e-5f
#define QSCALE_ 0.09016844270216718f   // log2(e)/sqrt(C)

// ---------------------------------------------------------------------------
// Device scratch
// ---------------------------------------------------------------------------
__device__ __half g_xh[(size_t)B_ * N_ * C_];    // GN-applied x, token-major
__device__ __half g_qh[(size_t)B_ * N_ * C_];    // Q token-major, pre-scaled
__device__ __half g_kh[(size_t)B_ * N_ * C_];    // K token-major
__device__ __half g_vh[(size_t)B_ * N_ * C_];    // V token-major
__device__ __half g_oh[(size_t)B_ * N_ * C_];    // attention out, token-major
__device__ __half g_wqh[3 * C_ * C_];            // w_qkv fp16 [o][c]
__device__ __half g_woh[C_ * C_];                // w_out fp16 [o][c]
__device__ float  g_fs[B_ * C_];
__device__ float  g_fb[B_ * C_];
__device__ float  g_p1[512];                     // GN partial sums
__device__ float  g_p2[512];

// ---------------------------------------------------------------------------
// Helpers
// ---------------------------------------------------------------------------
__device__ __forceinline__ void mma_f16(float* c,
    uint32_t a0, uint32_t a1, uint32_t a2, uint32_t a3,
    uint32_t b0, uint32_t b1)
{
    asm volatile(
        "mma.sync.aligned.m16n8k16.row.col.f32.f16.f16.f32 "
        "{%0,%1,%2,%3}, {%4,%5,%6,%7}, {%8,%9}, {%0,%1,%2,%3};"
        : "+f"(c[0]), "+f"(c[1]), "+f"(c[2]), "+f"(c[3])
        : "r"(a0), "r"(a1), "r"(a2), "r"(a3), "r"(b0), "r"(b1));
}
__device__ __forceinline__ void ldsm4(uint32_t& r0, uint32_t& r1,
                                      uint32_t& r2, uint32_t& r3, uint32_t addr)
{
    asm volatile("ldmatrix.sync.aligned.m8n8.x4.shared.b16 {%0,%1,%2,%3}, [%4];"
        : "=r"(r0), "=r"(r1), "=r"(r2), "=r"(r3) : "r"(addr));
}
__device__ __forceinline__ void ldsm4t(uint32_t& r0, uint32_t& r1,
                                       uint32_t& r2, uint32_t& r3, uint32_t addr)
{
    asm volatile("ldmatrix.sync.aligned.m8n8.x4.trans.shared.b16 {%0,%1,%2,%3}, [%4];"
        : "=r"(r0), "=r"(r1), "=r"(r2), "=r"(r3) : "r"(addr));
}
__device__ __forceinline__ float ex2f(float x) {
    float r;
    asm("ex2.approx.ftz.f32 %0, %1;" : "=f"(r) : "f"(x));
    return r;
}
__device__ __forceinline__ uint32_t fp2h2(float lo, float hi) {
    __half2 h = __floats2half2_rn(lo, hi);
    return *reinterpret_cast<uint32_t*>(&h);
}
__device__ __forceinline__ uint32_t smem_u32(const void* p) {
    uint32_t a;
    asm("{ .reg .u64 t; cvta.to.shared.u64 t, %1; cvt.u32.u64 %0, t; }"
        : "=r"(a) : "l"(p));
    return a;
}
__device__ __forceinline__ void cp16(uint32_t dst, const void* src) {
    asm volatile("cp.async.cg.shared.global [%0], [%1], 16;"
                 :: "r"(dst), "l"(src) : "memory");
}
#define CP_COMMIT() asm volatile("cp.async.commit_group;" ::: "memory")
#define CP_WAIT0()  asm volatile("cp.async.wait_group 0;" ::: "memory")

// ---------------------------------------------------------------------------
// Kernel 1a: GroupNorm partial sums. 512 CTAs (8 per (b,g)); deterministic.
// ---------------------------------------------------------------------------
__global__ __launch_bounds__(256) void gn_part_kernel(const float* __restrict__ x)
{
    int bg  = blockIdx.x >> 3;           // (b*8+g), 131072 contiguous floats
    int sub = blockIdx.x & 7;
    const float4* p = reinterpret_cast<const float4*>(x) +
                      (size_t)bg * 32768 + sub * 4096;
    float s1 = 0.f, s2 = 0.f;
    for (int i = threadIdx.x; i < 4096; i += 256) {
        float4 v = p[i];
        s1 += (v.x + v.y) + (v.z + v.w);
        s2 += (v.x * v.x + v.y * v.y) + (v.z * v.z + v.w * v.w);
    }
    #pragma unroll
    for (int off = 16; off; off >>= 1) {
        s1 += __shfl_xor_sync(0xffffffffu, s1, off);
        s2 += __shfl_xor_sync(0xffffffffu, s2, off);
    }
    __shared__ float a1[8], a2[8];
    int warp = threadIdx.x >> 5;
    if ((threadIdx.x & 31) == 0) { a1[warp] = s1; a2[warp] = s2; }
    __syncthreads();
    if (threadIdx.x == 0) {
        float t1 = 0.f, t2 = 0.f;
        #pragma unroll
        for (int w = 0; w < 8; w++) { t1 += a1[w]; t2 += a2[w]; }
        g_p1[blockIdx.x] = t1;
        g_p2[blockIdx.x] = t2;
    }
}

// ---------------------------------------------------------------------------
// Kernel 1b: GN finalize. 64 blocks x 32 threads -> fused fs/fb.
// ---------------------------------------------------------------------------
__global__ __launch_bounds__(32) void gn_fin_kernel(
    const float* __restrict__ gamma, const float* __restrict__ beta)
{
    int bg = blockIdx.x;
    int b  = bg >> 3, g = bg & 7;
    float t1 = 0.f, t2 = 0.f;
    #pragma unroll
    for (int k = 0; k < 8; k++) {
        t1 += g_p1[bg * 8 + k];
        t2 += g_p2[bg * 8 + k];
    }
    float mean = t1 * (1.f / 131072.f);
    float var  = t2 * (1.f / 131072.f) - mean * mean;
    float rstd = rsqrtf(var + EPS_);
    int c = g * CPG_ + threadIdx.x;
    float ga = gamma[c];
    float fs = rstd * ga;
    g_fs[b * C_ + c] = fs;
    g_fb[b * C_ + c] = beta[c] - mean * fs;
}

// ---------------------------------------------------------------------------
// Kernel 2a: weights fp32 -> fp16
// ---------------------------------------------------------------------------
__global__ __launch_bounds__(256) void wconv_kernel(
    const float* __restrict__ wq, const float* __restrict__ wo)
{
    int i = blockIdx.x * 256 + threadIdx.x;
    for (int k = i; k < 3 * C_ * C_; k += 65536)
        g_wqh[k] = __float2half(wq[k]);
    if (i < C_ * C_)
        g_woh[i] = __float2half(wo[i]);
}

// ---------------------------------------------------------------------------
// Kernel 2b: xn = GN(x) as fp16 token-major (B, N, C)
// ---------------------------------------------------------------------------
__global__ __launch_bounds__(256) void xn_half_kernel(const float* __restrict__ x)
{
    __shared__ float T[64][65];
    int n0 = blockIdx.x * 256;
    int c0 = blockIdx.y * 64;
    int b  = blockIdx.z;
    int tid = threadIdx.x;
    const float* fsb = g_fs + b * C_;
    const float* fbb = g_fb + b * C_;

    for (int s = 0; s < 4; s++) {
        int nn0 = n0 + s * 64;
        for (int idx = tid; idx < 1024; idx += 256) {
            int cc = idx >> 4, nn4 = (idx & 15) * 4;
            float4 v = *(const float4*)&x[((size_t)(b * C_ + c0 + cc)) * N_ + nn0 + nn4];
            float fs = fsb[c0 + cc], fb = fbb[c0 + cc];
            T[cc][nn4 + 0] = v.x * fs + fb;
            T[cc][nn4 + 1] = v.y * fs + fb;
            T[cc][nn4 + 2] = v.z * fs + fb;
            T[cc][nn4 + 3] = v.w * fs + fb;
        }
        __syncthreads();
        for (int idx = tid; idx < 2048; idx += 256) {
            int nn = idx >> 5, c = (idx & 31) * 2;
            *(uint32_t*)&g_xh[((size_t)b * N_ + nn0 + nn) * C_ + c0 + c] =
                fp2h2(T[c][nn], T[c + 1][nn]);
        }
        __syncthreads();
    }
}

// ---------------------------------------------------------------------------
// Kernel 3: QKV GEMM fp16 mma + ldmatrix. CTA = 128 tokens x 128 outputs
// (16 independent chains/warp). grid (N/128, 6, B); type = y>>1.
// ---------------------------------------------------------------------------
#define AP 264
#define HG_SMEM ((128 * AP + 128 * AP) * 2)   // 135168 B

__global__ __launch_bounds__(256) void qkv_hgemm_kernel(
    const float* __restrict__ bias)
{
    extern __shared__ __align__(16) char smraw[];
    __half* Ah = (__half*)smraw;
    __half* Bh = Ah + 128 * AP;

    int tid = threadIdx.x;
    int w = tid >> 5, lid = tid & 31;
    int g = lid >> 2, t = lid & 3;
    int wrow = w * 16;
    int n0 = blockIdx.x * 128;
    int o0 = blockIdx.y * 128;
    int b  = blockIdx.z;

    const __half* ag = g_xh + ((size_t)b * N_ + n0) * C_;
    const __half* bg = g_wqh + (size_t)o0 * C_;
    for (int idx = tid; idx < 4096; idx += 256) {
        int r = idx >> 5, c8 = idx & 31;
        *(uint4*)(Ah + r * AP + c8 * 8) = *(const uint4*)(ag + (size_t)r * C_ + c8 * 8);
        *(uint4*)(Bh + r * AP + c8 * 8) = *(const uint4*)(bg + (size_t)r * C_ + c8 * 8);
    }
    __syncthreads();

    uint32_t aa = smem_u32(Ah) +
        (uint32_t)(((wrow + (lid & 15)) * AP + (lid >> 4) * 8) * 2);
    uint32_t bb = smem_u32(Bh) +
        (uint32_t)(((((lid & 7) + ((lid >> 4) & 1) * 8)) * AP + ((lid >> 3) & 1) * 8) * 2);

    float acc[16][4];
    #pragma unroll
    for (int nb = 0; nb < 16; nb++)
        #pragma unroll
        for (int j = 0; j < 4; j++) acc[nb][j] = 0.f;

    #pragma unroll 4
    for (int kk = 0; kk < 16; kk++) {
        uint32_t a0, a1, a2, a3;
        ldsm4(a0, a1, a2, a3, aa + kk * 32);
        #pragma unroll
        for (int nbp = 0; nbp < 8; nbp++) {
            uint32_t b0, b1, b2, b3;
            ldsm4(b0, b1, b2, b3, bb + (nbp * 16 * AP + kk * 16) * 2);
            mma_f16(acc[2 * nbp],     a0, a1, a2, a3, b0, b1);
            mma_f16(acc[2 * nbp + 1], a0, a1, a2, a3, b2, b3);
        }
    }

    int type = blockIdx.y >> 1;           // 0 Q, 1 K, 2 V
    int n_lo = n0 + wrow + g;
    float scale = (type == 0) ? QSCALE_ : 1.f;
    __half* gdst = (type == 0 ? g_qh : (type == 1 ? g_kh : g_vh));
    #pragma unroll
    for (int nb = 0; nb < 16; nb++) {
        int og = o0 + nb * 8 + 2 * t;
        int oo = og & 255;
        float b0v = bias[og], b1v = bias[og + 1];
        __half* dst = gdst + ((size_t)b * N_ + n_lo) * C_ + oo;
        *(uint32_t*)dst = fp2h2((acc[nb][0] + b0v) * scale, (acc[nb][1] + b1v) * scale);
        *(uint32_t*)(dst + 8 * C_) = fp2h2((acc[nb][2] + b0v) * scale, (acc[nb][3] + b1v) * scale);
    }
}

// ---------------------------------------------------------------------------
// Kernel 4: flash attention (UNCHANGED from R14): 256 thr / 8 warps,
// KB=64 (64 iters, 8 S-chains), 2-stage cp.async ring, register P,
// V token-major via ldsm.trans.
// ---------------------------------------------------------------------------
#define QPH 264
#define KPH 264
#define VP2 264
#define QWH (128 * QPH)
#define KWH (64 * KPH)
#define VWH (64 * VP2)
#define FL_SMEM ((QWH + 2 * KWH + 2 * VWH) * 2)   // 202752 B

__global__ void __launch_bounds__(256, 1) flash_kernel()
{
    extern __shared__ __align__(16) char smraw[];
    __half* Qh = (__half*)smraw;
    uint32_t sb = smem_u32(smraw);
    uint32_t ka[2], va[2];
    #pragma unroll
    for (int s = 0; s < 2; s++) {
        ka[s] = sb + (QWH + s * KWH) * 2;
        va[s] = sb + (QWH + 2 * KWH + s * VWH) * 2;
    }

    int tid = threadIdx.x;
    int w   = tid >> 5;
    int lid = tid & 31;
    int b   = blockIdx.y;
    int n0  = blockIdx.x * 128;
    int wrow = w * 16;

    const __half* qg = g_qh + ((size_t)b * N_ + n0) * C_;
    const __half* kg = g_kh + (size_t)b * N_ * C_;
    const __half* vg = g_vh + (size_t)b * N_ * C_;

    int kr = tid >> 5, kc8 = tid & 31;

    #pragma unroll
    for (int rr = 0; rr < 64; rr += 8) {
        cp16(ka[0] + ((kr + rr) * KPH + kc8 * 8) * 2,
             kg + (size_t)(kr + rr) * C_ + kc8 * 8);
        cp16(va[0] + ((kr + rr) * VP2 + kc8 * 8) * 2,
             vg + (size_t)(kr + rr) * C_ + kc8 * 8);
    }
    CP_COMMIT();

    for (int idx = tid; idx < 4096; idx += 256) {
        int r = idx >> 5, c8 = idx & 31;
        *(uint4*)(Qh + r * QPH + c8 * 8) =
            *(const uint4*)(qg + (size_t)r * C_ + c8 * 8);
    }

    uint32_t qa = sb + (uint32_t)(((wrow + (lid & 15)) * QPH + (lid >> 4) * 8) * 2);
    uint32_t kbo = (uint32_t)(((((lid & 7) + ((lid >> 4) & 1) * 8)) * KPH
                               + ((lid >> 3) & 1) * 8) * 2);
    uint32_t vbo = (uint32_t)((((lid & 7) + ((lid >> 3) & 1) * 8) * VP2
                               + (lid >> 4) * 8) * 2);

    float Oacc[32][4];
    #pragma unroll
    for (int nb = 0; nb < 32; nb++)
        #pragma unroll
        for (int j = 0; j < 4; j++) Oacc[nb][j] = 0.f;
    float lsum_lo = 0.f, lsum_hi = 0.f;

    for (int i = 0; i < 64; i++) {
        CP_WAIT0();
        __syncthreads();
        if (i < 63) {
            int j = i + 1;
            uint32_t kd = ka[j & 1], vd = va[j & 1];
            #pragma unroll
            for (int rr = 0; rr < 64; rr += 8) {
                cp16(kd + ((kr + rr) * KPH + kc8 * 8) * 2,
                     kg + (size_t)(j * 64 + kr + rr) * C_ + kc8 * 8);
                cp16(vd + ((kr + rr) * VP2 + kc8 * 8) * 2,
                     vg + (size_t)(j * 64 + kr + rr) * C_ + kc8 * 8);
            }
            CP_COMMIT();
        }

        uint32_t kbuf = ka[i & 1] + kbo;
        uint32_t vbuf = va[i & 1] + vbo;

        float s[8][4];
        #pragma unroll
        for (int nb = 0; nb < 8; nb++)
            #pragma unroll
            for (int j = 0; j < 4; j++) s[nb][j] = 0.f;
        #pragma unroll 4
        for (int kk = 0; kk < 16; kk++) {
            uint32_t a0, a1, a2, a3;
            ldsm4(a0, a1, a2, a3, qa + kk * 32);
            #pragma unroll
            for (int nbp = 0; nbp < 4; nbp++) {
                uint32_t b0, b1, b2, b3;
                ldsm4(b0, b1, b2, b3, kbuf + (nbp * 16 * KPH + kk * 16) * 2);
                mma_f16(s[2 * nbp],     a0, a1, a2, a3, b0, b1);
                mma_f16(s[2 * nbp + 1], a0, a1, a2, a3, b2, b3);
            }
        }

        float e[8][4];
        #pragma unroll
        for (int nb = 0; nb < 8; nb++) {
            e[nb][0] = ex2f(s[nb][0]);
            e[nb][1] = ex2f(s[nb][1]);
            e[nb][2] = ex2f(s[nb][2]);
            e[nb][3] = ex2f(s[nb][3]);
            lsum_lo += e[nb][0] + e[nb][1];
            lsum_hi += e[nb][2] + e[nb][3];
        }
        uint32_t pf[4][4];
        #pragma unroll
        for (int j = 0; j < 4; j++) {
            pf[j][0] = fp2h2(e[2 * j][0],     e[2 * j][1]);
            pf[j][1] = fp2h2(e[2 * j][2],     e[2 * j][3]);
            pf[j][2] = fp2h2(e[2 * j + 1][0], e[2 * j + 1][1]);
            pf[j][3] = fp2h2(e[2 * j + 1][2], e[2 * j + 1][3]);
        }

        #pragma unroll 4
        for (int nbp = 0; nbp < 16; nbp++) {
            #pragma unroll
            for (int j = 0; j < 4; j++) {
                uint32_t b0, b1, b2, b3;
                ldsm4t(b0, b1, b2, b3, vbuf + (j * 16 * VP2 + nbp * 16) * 2);
                mma_f16(Oacc[2 * nbp],     pf[j][0], pf[j][1], pf[j][2], pf[j][3], b0, b1);
                mma_f16(Oacc[2 * nbp + 1], pf[j][0], pf[j][1], pf[j][2], pf[j][3], b2, b3);
            }
        }
    }

    lsum_lo += __shfl_xor_sync(0xffffffffu, lsum_lo, 1);
    lsum_lo += __shfl_xor_sync(0xffffffffu, lsum_lo, 2);
    lsum_hi += __shfl_xor_sync(0xffffffffu, lsum_hi, 1);
    lsum_hi += __shfl_xor_sync(0xffffffffu, lsum_hi, 2);
    float inv_lo = 1.f / lsum_lo;
    float inv_hi = 1.f / lsum_hi;

    int g = lid >> 2, t = lid & 3;
    __half* od = g_oh + ((size_t)b * N_ + n0 + wrow + g) * C_;
    #pragma unroll
    for (int nb = 0; nb < 32; nb++) {
        int c = nb * 8 + 2 * t;
        *(uint32_t*)(od + c) = fp2h2(Oacc[nb][0] * inv_lo, Oacc[nb][1] * inv_lo);
        *(uint32_t*)(od + 8 * C_ + c) = fp2h2(Oacc[nb][2] * inv_hi, Oacc[nb][3] * inv_hi);
    }
}

// ---------------------------------------------------------------------------
// Kernel 5: output projection fp16 mma + ldmatrix + bias + residual.
// CTA = 128 tokens x 128 outputs (16 chains). grid (N/128, 2, B).
// ---------------------------------------------------------------------------
__global__ __launch_bounds__(256) void proj_hgemm_kernel(
    const float* __restrict__ bias,
    const float* __restrict__ x,
    float* __restrict__ out)
{
    extern __shared__ __align__(16) char smraw[];
    __half* Ah = (__half*)smraw;
    __half* Bh = Ah + 128 * AP;
    float* Ts  = (float*)smraw;          // reused after compute: 128 x 136

    int tid = threadIdx.x;
    int w = tid >> 5, lid = tid & 31;
    int g = lid >> 2, t = lid & 3;
    int wrow = w * 16;
    int n0 = blockIdx.x * 128;
    int o0 = blockIdx.y * 128;
    int b  = blockIdx.z;

    const __half* ag = g_oh + ((size_t)b * N_ + n0) * C_;
    const __half* bg = g_woh + (size_t)o0 * C_;
    for (int idx = tid; idx < 4096; idx += 256) {
        int r = idx >> 5, c8 = idx & 31;
        *(uint4*)(Ah + r * AP + c8 * 8) = *(const uint4*)(ag + (size_t)r * C_ + c8 * 8);
        *(uint4*)(Bh + r * AP + c8 * 8) = *(const uint4*)(bg + (size_t)r * C_ + c8 * 8);
    }
    __syncthreads();

    uint32_t aa = smem_u32(Ah) +
        (uint32_t)(((wrow + (lid & 15)) * AP + (lid >> 4) * 8) * 2);
    uint32_t bb = smem_u32(Bh) +
        (uint32_t)(((((lid & 7) + ((lid >> 4) & 1) * 8)) * AP + ((lid >> 3) & 1) * 8) * 2);

    float acc[16][4];
    #pragma unroll
    for (int nb = 0; nb < 16; nb++)
        #pragma unroll
        for (int j = 0; j < 4; j++) acc[nb][j] = 0.f;

    #pragma unroll 4
    for (int kk = 0; kk < 16; kk++) {
        uint32_t a0, a1, a2, a3;
        ldsm4(a0, a1, a2, a3, aa + kk * 32);
        #pragma unroll
        for (int nbp = 0; nbp < 8; nbp++) {
            uint32_t b0, b1, b2, b3;
            ldsm4(b0, b1, b2, b3, bb + (nbp * 16 * AP + kk * 16) * 2);
            mma_f16(acc[2 * nbp],     a0, a1, a2, a3, b0, b1);
            mma_f16(acc[2 * nbp + 1], a0, a1, a2, a3, b2, b3);
        }
    }

    // stage D transposed [o_local][token] in fp32
    __syncthreads();
    #pragma unroll
    for (int nb = 0; nb < 16; nb++) {
        int ol = nb * 8 + 2 * t;
        Ts[ol * 136 + wrow + g]           = acc[nb][0];
        Ts[(ol + 1) * 136 + wrow + g]     = acc[nb][1];
        Ts[ol * 136 + wrow + g + 8]       = acc[nb][2];
        Ts[(ol + 1) * 136 + wrow + g + 8] = acc[nb][3];
    }
    __syncthreads();

    for (int idx = tid; idx < 4096; idx += 256) {
        int o = idx >> 5, n4 = (idx & 31) * 4;
        int og = o0 + o;
        float bo = bias[og];
        size_t base = ((size_t)b * C_ + og) * N_ + n0 + n4;
        float4 res = *(const float4*)&x[base];
        float4 d   = *(const float4*)&Ts[o * 136 + n4];
        float4 r = make_float4(d.x + bo + res.x, d.y + bo + res.y,
                               d.z + bo + res.z, d.w + bo + res.w);
        *(float4*)&out[base] = r;
    }
}

// ---------------------------------------------------------------------------
// Launch
// ---------------------------------------------------------------------------
extern "C" void kernel_launch(void* const* d_in, const int* in_sizes, int n_in,
                              void* d_out, int out_size)
{
    const float* x        = (const float*)d_in[0];
    const float* gn_scale = (const float*)d_in[1];
    const float* gn_bias  = (const float*)d_in[2];
    const float* w_qkv    = (const float*)d_in[3];
    const float* b_qkv    = (const float*)d_in[4];
    const float* w_out    = (const float*)d_in[5];
    const float* b_out    = (const float*)d_in[6];
    float* out = (float*)d_out;

    cudaFuncSetAttribute(flash_kernel,
                         cudaFuncAttributeMaxDynamicSharedMemorySize, FL_SMEM);
    cudaFuncSetAttribute(qkv_hgemm_kernel,
                         cudaFuncAttributeMaxDynamicSharedMemorySize, HG_SMEM);
    cudaFuncSetAttribute(proj_hgemm_kernel,
                         cudaFuncAttributeMaxDynamicSharedMemorySize, HG_SMEM);

    wconv_kernel<<<256, 256>>>(w_qkv, w_out);
    gn_part_kernel<<<512, 256>>>(x);
    gn_fin_kernel<<<64, 32>>>(gn_scale, gn_bias);
    xn_half_kernel<<<dim3(N_ / 256, C_ / 64, B_), 256>>>(x);
    qkv_hgemm_kernel<<<dim3(N_ / 128, 6, B_), 256, HG_SMEM>>>(b_qkv);
    flash_kernel<<<dim3(N_ / 128, B_), 256, FL_SMEM>>>();
    proj_hgemm_kernel<<<dim3(N_ / 128, 2, B_), 256, HG_SMEM>>>(b_out, x, out);
}

// round 17
// speedup vs baseline: 1.0148x; 1.0148x over previous
#include <cuda_runtime.h>
#include <cuda_fp16.h>
#include <cstdint>

// ---------------------------------------------------------------------------
// Problem constants
// ---------------------------------------------------------------------------
#define B_   8
#define C_   256
#define N_   4096
#define G_   8
#define CPG_ 32
#define EPS_ 1e-5f
#define QSCALE_ 0.09016844270216718f   // log2(e)/sqrt(C)

// ---------------------------------------------------------------------------
// Device scratch
// ---------------------------------------------------------------------------
__device__ __half g_xh[(size_t)B_ * N_ * C_];    // GN-applied x, token-major
__device__ __half g_qh[(size_t)B_ * N_ * C_];    // Q token-major, pre-scaled
__device__ __half g_kh[(size_t)B_ * N_ * C_];    // K token-major
__device__ __half g_vh[(size_t)B_ * N_ * C_];    // V token-major
__device__ __half g_oh[(size_t)B_ * N_ * C_];    // attention out, token-major
__device__ __half g_wqh[3 * C_ * C_];            // w_qkv fp16 [o][c]
__device__ __half g_woh[C_ * C_];                // w_out fp16 [o][c]
__device__ float  g_fs[B_ * C_];
__device__ float  g_fb[B_ * C_];
__device__ float  g_p1[512];                     // GN partial sums
__device__ float  g_p2[512];

// ---------------------------------------------------------------------------
// Helpers
// ---------------------------------------------------------------------------
__device__ __forceinline__ void mma_f16(float* c,
    uint32_t a0, uint32_t a1, uint32_t a2, uint32_t a3,
    uint32_t b0, uint32_t b1)
{
    asm volatile(
        "mma.sync.aligned.m16n8k16.row.col.f32.f16.f16.f32 "
        "{%0,%1,%2,%3}, {%4,%5,%6,%7}, {%8,%9}, {%0,%1,%2,%3};"
        : "+f"(c[0]), "+f"(c[1]), "+f"(c[2]), "+f"(c[3])
        : "r"(a0), "r"(a1), "r"(a2), "r"(a3), "r"(b0), "r"(b1));
}
__device__ __forceinline__ void ldsm4(uint32_t& r0, uint32_t& r1,
                                      uint32_t& r2, uint32_t& r3, uint32_t addr)
{
    asm volatile("ldmatrix.sync.aligned.m8n8.x4.shared.b16 {%0,%1,%2,%3}, [%4];"
        : "=r"(r0), "=r"(r1), "=r"(r2), "=r"(r3) : "r"(addr));
}
__device__ __forceinline__ void ldsm4t(uint32_t& r0, uint32_t& r1,
                                       uint32_t& r2, uint32_t& r3, uint32_t addr)
{
    asm volatile("ldmatrix.sync.aligned.m8n8.x4.trans.shared.b16 {%0,%1,%2,%3}, [%4];"
        : "=r"(r0), "=r"(r1), "=r"(r2), "=r"(r3) : "r"(addr));
}
__device__ __forceinline__ float ex2f(float x) {
    float r;
    asm("ex2.approx.ftz.f32 %0, %1;" : "=f"(r) : "f"(x));
    return r;
}
__device__ __forceinline__ uint32_t fp2h2(float lo, float hi) {
    __half2 h = __floats2half2_rn(lo, hi);
    return *reinterpret_cast<uint32_t*>(&h);
}
__device__ __forceinline__ uint32_t smem_u32(const void* p) {
    uint32_t a;
    asm("{ .reg .u64 t; cvta.to.shared.u64 t, %1; cvt.u32.u64 %0, t; }"
        : "=r"(a) : "l"(p));
    return a;
}
__device__ __forceinline__ void cp16(uint32_t dst, const void* src) {
    asm volatile("cp.async.cg.shared.global [%0], [%1], 16;"
                 :: "r"(dst), "l"(src) : "memory");
}
#define CP_COMMIT() asm volatile("cp.async.commit_group;" ::: "memory")
#define CP_WAIT0()  asm volatile("cp.async.wait_group 0;" ::: "memory")

// ---------------------------------------------------------------------------
// Kernel 1a: GroupNorm partial sums. 512 CTAs; deterministic.
// ---------------------------------------------------------------------------
__global__ __launch_bounds__(256) void gn_part_kernel(const float* __restrict__ x)
{
    int bg  = blockIdx.x >> 3;
    int sub = blockIdx.x & 7;
    const float4* p = reinterpret_cast<const float4*>(x) +
                      (size_t)bg * 32768 + sub * 4096;
    float s1 = 0.f, s2 = 0.f;
    for (int i = threadIdx.x; i < 4096; i += 256) {
        float4 v = p[i];
        s1 += (v.x + v.y) + (v.z + v.w);
        s2 += (v.x * v.x + v.y * v.y) + (v.z * v.z + v.w * v.w);
    }
    #pragma unroll
    for (int off = 16; off; off >>= 1) {
        s1 += __shfl_xor_sync(0xffffffffu, s1, off);
        s2 += __shfl_xor_sync(0xffffffffu, s2, off);
    }
    __shared__ float a1[8], a2[8];
    int warp = threadIdx.x >> 5;
    if ((threadIdx.x & 31) == 0) { a1[warp] = s1; a2[warp] = s2; }
    __syncthreads();
    if (threadIdx.x == 0) {
        float t1 = 0.f, t2 = 0.f;
        #pragma unroll
        for (int w = 0; w < 8; w++) { t1 += a1[w]; t2 += a2[w]; }
        g_p1[blockIdx.x] = t1;
        g_p2[blockIdx.x] = t2;
    }
}

// ---------------------------------------------------------------------------
// Kernel 1b: GN finalize. 64 blocks x 32 threads -> fused fs/fb.
// ---------------------------------------------------------------------------
__global__ __launch_bounds__(32) void gn_fin_kernel(
    const float* __restrict__ gamma, const float* __restrict__ beta)
{
    int bg = blockIdx.x;
    int b  = bg >> 3, g = bg & 7;
    float t1 = 0.f, t2 = 0.f;
    #pragma unroll
    for (int k = 0; k < 8; k++) {
        t1 += g_p1[bg * 8 + k];
        t2 += g_p2[bg * 8 + k];
    }
    float mean = t1 * (1.f / 131072.f);
    float var  = t2 * (1.f / 131072.f) - mean * mean;
    float rstd = rsqrtf(var + EPS_);
    int c = g * CPG_ + threadIdx.x;
    float ga = gamma[c];
    float fs = rstd * ga;
    g_fs[b * C_ + c] = fs;
    g_fb[b * C_ + c] = beta[c] - mean * fs;
}

// ---------------------------------------------------------------------------
// Kernel 2a: weights fp32 -> fp16
// ---------------------------------------------------------------------------
__global__ __launch_bounds__(256) void wconv_kernel(
    const float* __restrict__ wq, const float* __restrict__ wo)
{
    int i = blockIdx.x * 256 + threadIdx.x;
    for (int k = i; k < 3 * C_ * C_; k += 65536)
        g_wqh[k] = __float2half(wq[k]);
    if (i < C_ * C_)
        g_woh[i] = __float2half(wo[i]);
}

// ---------------------------------------------------------------------------
// Kernel 2b: xn = GN(x) as fp16 token-major (B, N, C)
// ---------------------------------------------------------------------------
__global__ __launch_bounds__(256) void xn_half_kernel(const float* __restrict__ x)
{
    __shared__ float T[64][65];
    int n0 = blockIdx.x * 256;
    int c0 = blockIdx.y * 64;
    int b  = blockIdx.z;
    int tid = threadIdx.x;
    const float* fsb = g_fs + b * C_;
    const float* fbb = g_fb + b * C_;

    for (int s = 0; s < 4; s++) {
        int nn0 = n0 + s * 64;
        for (int idx = tid; idx < 1024; idx += 256) {
            int cc = idx >> 4, nn4 = (idx & 15) * 4;
            float4 v = *(const float4*)&x[((size_t)(b * C_ + c0 + cc)) * N_ + nn0 + nn4];
            float fs = fsb[c0 + cc], fb = fbb[c0 + cc];
            T[cc][nn4 + 0] = v.x * fs + fb;
            T[cc][nn4 + 1] = v.y * fs + fb;
            T[cc][nn4 + 2] = v.z * fs + fb;
            T[cc][nn4 + 3] = v.w * fs + fb;
        }
        __syncthreads();
        for (int idx = tid; idx < 2048; idx += 256) {
            int nn = idx >> 5, c = (idx & 31) * 2;
            *(uint32_t*)&g_xh[((size_t)b * N_ + nn0 + nn) * C_ + c0 + c] =
                fp2h2(T[c][nn], T[c + 1][nn]);
        }
        __syncthreads();
    }
}

// ---------------------------------------------------------------------------
// Kernel 3: QKV GEMM fp16 mma + ldmatrix, split-K dual accumulators.
// CTA = 128 tokens x 64 outputs (2 CTAs/SM), 16 independent chains/warp.
// grid (N/128, 12, B); type = y>>2.
// ---------------------------------------------------------------------------
#define AP 264
#define HG_SMEM ((128 * AP + 64 * AP) * 2)   // 101376 B

__global__ __launch_bounds__(256) void qkv_hgemm_kernel(
    const float* __restrict__ bias)
{
    extern __shared__ __align__(16) char smraw[];
    __half* Ah = (__half*)smraw;
    __half* Bh = Ah + 128 * AP;

    int tid = threadIdx.x;
    int w = tid >> 5, lid = tid & 31;
    int g = lid >> 2, t = lid & 3;
    int wrow = w * 16;
    int n0 = blockIdx.x * 128;
    int o0 = blockIdx.y * 64;
    int b  = blockIdx.z;

    const __half* ag = g_xh + ((size_t)b * N_ + n0) * C_;
    const __half* bg = g_wqh + (size_t)o0 * C_;
    for (int idx = tid; idx < 4096; idx += 256) {
        int r = idx >> 5, c8 = idx & 31;
        *(uint4*)(Ah + r * AP + c8 * 8) = *(const uint4*)(ag + (size_t)r * C_ + c8 * 8);
    }
    for (int idx = tid; idx < 2048; idx += 256) {
        int r = idx >> 5, c8 = idx & 31;
        *(uint4*)(Bh + r * AP + c8 * 8) = *(const uint4*)(bg + (size_t)r * C_ + c8 * 8);
    }
    __syncthreads();

    uint32_t aa = smem_u32(Ah) +
        (uint32_t)(((wrow + (lid & 15)) * AP + (lid >> 4) * 8) * 2);
    uint32_t bb = smem_u32(Bh) +
        (uint32_t)(((((lid & 7) + ((lid >> 4) & 1) * 8)) * AP + ((lid >> 3) & 1) * 8) * 2);

    float acc0[8][4], acc1[8][4];
    #pragma unroll
    for (int nb = 0; nb < 8; nb++)
        #pragma unroll
        for (int j = 0; j < 4; j++) { acc0[nb][j] = 0.f; acc1[nb][j] = 0.f; }

    // split-K: kk and kk+8 run as independent chains (16 chains live)
    #pragma unroll 2
    for (int kk = 0; kk < 8; kk++) {
        uint32_t a0, a1, a2, a3, c0r, c1r, c2r, c3r;
        ldsm4(a0, a1, a2, a3, aa + kk * 32);
        ldsm4(c0r, c1r, c2r, c3r, aa + (kk + 8) * 32);
        #pragma unroll
        for (int nbp = 0; nbp < 4; nbp++) {
            uint32_t b0, b1, b2, b3, d0, d1, d2, d3;
            ldsm4(b0, b1, b2, b3, bb + (nbp * 16 * AP + kk * 16) * 2);
            ldsm4(d0, d1, d2, d3, bb + (nbp * 16 * AP + (kk + 8) * 16) * 2);
            mma_f16(acc0[2 * nbp],     a0, a1, a2, a3, b0, b1);
            mma_f16(acc0[2 * nbp + 1], a0, a1, a2, a3, b2, b3);
            mma_f16(acc1[2 * nbp],     c0r, c1r, c2r, c3r, d0, d1);
            mma_f16(acc1[2 * nbp + 1], c0r, c1r, c2r, c3r, d2, d3);
        }
    }

    int type = blockIdx.y >> 2;           // 0 Q, 1 K, 2 V
    int n_lo = n0 + wrow + g;
    float scale = (type == 0) ? QSCALE_ : 1.f;
    __half* gdst = (type == 0 ? g_qh : (type == 1 ? g_kh : g_vh));
    #pragma unroll
    for (int nb = 0; nb < 8; nb++) {
        int og = o0 + nb * 8 + 2 * t;
        int oo = og & 255;
        float b0v = bias[og], b1v = bias[og + 1];
        float v0 = acc0[nb][0] + acc1[nb][0] + b0v;
        float v1 = acc0[nb][1] + acc1[nb][1] + b1v;
        float v2 = acc0[nb][2] + acc1[nb][2] + b0v;
        float v3 = acc0[nb][3] + acc1[nb][3] + b1v;
        __half* dst = gdst + ((size_t)b * N_ + n_lo) * C_ + oo;
        *(uint32_t*)dst = fp2h2(v0 * scale, v1 * scale);
        *(uint32_t*)(dst + 8 * C_) = fp2h2(v2 * scale, v3 * scale);
    }
}

// ---------------------------------------------------------------------------
// Kernel 4: flash attention (UNCHANGED from R14): 256 thr / 8 warps,
// KB=64 (64 iters, 8 S-chains), 2-stage cp.async ring, register P,
// V token-major via ldsm.trans.
// ---------------------------------------------------------------------------
#define QPH 264
#define KPH 264
#define VP2 264
#define QWH (128 * QPH)
#define KWH (64 * KPH)
#define VWH (64 * VP2)
#define FL_SMEM ((QWH + 2 * KWH + 2 * VWH) * 2)   // 202752 B

__global__ void __launch_bounds__(256, 1) flash_kernel()
{
    extern __shared__ __align__(16) char smraw[];
    __half* Qh = (__half*)smraw;
    uint32_t sb = smem_u32(smraw);
    uint32_t ka[2], va[2];
    #pragma unroll
    for (int s = 0; s < 2; s++) {
        ka[s] = sb + (QWH + s * KWH) * 2;
        va[s] = sb + (QWH + 2 * KWH + s * VWH) * 2;
    }

    int tid = threadIdx.x;
    int w   = tid >> 5;
    int lid = tid & 31;
    int b   = blockIdx.y;
    int n0  = blockIdx.x * 128;
    int wrow = w * 16;

    const __half* qg = g_qh + ((size_t)b * N_ + n0) * C_;
    const __half* kg = g_kh + (size_t)b * N_ * C_;
    const __half* vg = g_vh + (size_t)b * N_ * C_;

    int kr = tid >> 5, kc8 = tid & 31;

    #pragma unroll
    for (int rr = 0; rr < 64; rr += 8) {
        cp16(ka[0] + ((kr + rr) * KPH + kc8 * 8) * 2,
             kg + (size_t)(kr + rr) * C_ + kc8 * 8);
        cp16(va[0] + ((kr + rr) * VP2 + kc8 * 8) * 2,
             vg + (size_t)(kr + rr) * C_ + kc8 * 8);
    }
    CP_COMMIT();

    for (int idx = tid; idx < 4096; idx += 256) {
        int r = idx >> 5, c8 = idx & 31;
        *(uint4*)(Qh + r * QPH + c8 * 8) =
            *(const uint4*)(qg + (size_t)r * C_ + c8 * 8);
    }

    uint32_t qa = sb + (uint32_t)(((wrow + (lid & 15)) * QPH + (lid >> 4) * 8) * 2);
    uint32_t kbo = (uint32_t)(((((lid & 7) + ((lid >> 4) & 1) * 8)) * KPH
                               + ((lid >> 3) & 1) * 8) * 2);
    uint32_t vbo = (uint32_t)((((lid & 7) + ((lid >> 3) & 1) * 8) * VP2
                               + (lid >> 4) * 8) * 2);

    float Oacc[32][4];
    #pragma unroll
    for (int nb = 0; nb < 32; nb++)
        #pragma unroll
        for (int j = 0; j < 4; j++) Oacc[nb][j] = 0.f;
    float lsum_lo = 0.f, lsum_hi = 0.f;

    for (int i = 0; i < 64; i++) {
        CP_WAIT0();
        __syncthreads();
        if (i < 63) {
            int j = i + 1;
            uint32_t kd = ka[j & 1], vd = va[j & 1];
            #pragma unroll
            for (int rr = 0; rr < 64; rr += 8) {
                cp16(kd + ((kr + rr) * KPH + kc8 * 8) * 2,
                     kg + (size_t)(j * 64 + kr + rr) * C_ + kc8 * 8);
                cp16(vd + ((kr + rr) * VP2 + kc8 * 8) * 2,
                     vg + (size_t)(j * 64 + kr + rr) * C_ + kc8 * 8);
            }
            CP_COMMIT();
        }

        uint32_t kbuf = ka[i & 1] + kbo;
        uint32_t vbuf = va[i & 1] + vbo;

        float s[8][4];
        #pragma unroll
        for (int nb = 0; nb < 8; nb++)
            #pragma unroll
            for (int j = 0; j < 4; j++) s[nb][j] = 0.f;
        #pragma unroll 4
        for (int kk = 0; kk < 16; kk++) {
            uint32_t a0, a1, a2, a3;
            ldsm4(a0, a1, a2, a3, qa + kk * 32);
            #pragma unroll
            for (int nbp = 0; nbp < 4; nbp++) {
                uint32_t b0, b1, b2, b3;
                ldsm4(b0, b1, b2, b3, kbuf + (nbp * 16 * KPH + kk * 16) * 2);
                mma_f16(s[2 * nbp],     a0, a1, a2, a3, b0, b1);
                mma_f16(s[2 * nbp + 1], a0, a1, a2, a3, b2, b3);
            }
        }

        float e[8][4];
        #pragma unroll
        for (int nb = 0; nb < 8; nb++) {
            e[nb][0] = ex2f(s[nb][0]);
            e[nb][1] = ex2f(s[nb][1]);
            e[nb][2] = ex2f(s[nb][2]);
            e[nb][3] = ex2f(s[nb][3]);
            lsum_lo += e[nb][0] + e[nb][1];
            lsum_hi += e[nb][2] + e[nb][3];
        }
        uint32_t pf[4][4];
        #pragma unroll
        for (int j = 0; j < 4; j++) {
            pf[j][0] = fp2h2(e[2 * j][0],     e[2 * j][1]);
            pf[j][1] = fp2h2(e[2 * j][2],     e[2 * j][3]);
            pf[j][2] = fp2h2(e[2 * j + 1][0], e[2 * j + 1][1]);
            pf[j][3] = fp2h2(e[2 * j + 1][2], e[2 * j + 1][3]);
        }

        #pragma unroll 4
        for (int nbp = 0; nbp < 16; nbp++) {
            #pragma unroll
            for (int j = 0; j < 4; j++) {
                uint32_t b0, b1, b2, b3;
                ldsm4t(b0, b1, b2, b3, vbuf + (j * 16 * VP2 + nbp * 16) * 2);
                mma_f16(Oacc[2 * nbp],     pf[j][0], pf[j][1], pf[j][2], pf[j][3], b0, b1);
                mma_f16(Oacc[2 * nbp + 1], pf[j][0], pf[j][1], pf[j][2], pf[j][3], b2, b3);
            }
        }
    }

    lsum_lo += __shfl_xor_sync(0xffffffffu, lsum_lo, 1);
    lsum_lo += __shfl_xor_sync(0xffffffffu, lsum_lo, 2);
    lsum_hi += __shfl_xor_sync(0xffffffffu, lsum_hi, 1);
    lsum_hi += __shfl_xor_sync(0xffffffffu, lsum_hi, 2);
    float inv_lo = 1.f / lsum_lo;
    float inv_hi = 1.f / lsum_hi;

    int g = lid >> 2, t = lid & 3;
    __half* od = g_oh + ((size_t)b * N_ + n0 + wrow + g) * C_;
    #pragma unroll
    for (int nb = 0; nb < 32; nb++) {
        int c = nb * 8 + 2 * t;
        *(uint32_t*)(od + c) = fp2h2(Oacc[nb][0] * inv_lo, Oacc[nb][1] * inv_lo);
        *(uint32_t*)(od + 8 * C_ + c) = fp2h2(Oacc[nb][2] * inv_hi, Oacc[nb][3] * inv_hi);
    }
}

// ---------------------------------------------------------------------------
// Kernel 5: output projection, split-K dual accumulators, 128x64 tile,
// 2 CTAs/SM. grid (N/128, 4, B).
// ---------------------------------------------------------------------------
__global__ __launch_bounds__(256) void proj_hgemm_kernel(
    const float* __restrict__ bias,
    const float* __restrict__ x,
    float* __restrict__ out)
{
    extern __shared__ __align__(16) char smraw[];
    __half* Ah = (__half*)smraw;
    __half* Bh = Ah + 128 * AP;
    float* Ts  = (float*)smraw;          // reused after compute: 64 x 136

    int tid = threadIdx.x;
    int w = tid >> 5, lid = tid & 31;
    int g = lid >> 2, t = lid & 3;
    int wrow = w * 16;
    int n0 = blockIdx.x * 128;
    int o0 = blockIdx.y * 64;
    int b  = blockIdx.z;

    const __half* ag = g_oh + ((size_t)b * N_ + n0) * C_;
    const __half* bg = g_woh + (size_t)o0 * C_;
    for (int idx = tid; idx < 4096; idx += 256) {
        int r = idx >> 5, c8 = idx & 31;
        *(uint4*)(Ah + r * AP + c8 * 8) = *(const uint4*)(ag + (size_t)r * C_ + c8 * 8);
    }
    for (int idx = tid; idx < 2048; idx += 256) {
        int r = idx >> 5, c8 = idx & 31;
        *(uint4*)(Bh + r * AP + c8 * 8) = *(const uint4*)(bg + (size_t)r * C_ + c8 * 8);
    }
    __syncthreads();

    uint32_t aa = smem_u32(Ah) +
        (uint32_t)(((wrow + (lid & 15)) * AP + (lid >> 4) * 8) * 2);
    uint32_t bb = smem_u32(Bh) +
        (uint32_t)(((((lid & 7) + ((lid >> 4) & 1) * 8)) * AP + ((lid >> 3) & 1) * 8) * 2);

    float acc0[8][4], acc1[8][4];
    #pragma unroll
    for (int nb = 0; nb < 8; nb++)
        #pragma unroll
        for (int j = 0; j < 4; j++) { acc0[nb][j] = 0.f; acc1[nb][j] = 0.f; }

    #pragma unroll 2
    for (int kk = 0; kk < 8; kk++) {
        uint32_t a0, a1, a2, a3, c0r, c1r, c2r, c3r;
        ldsm4(a0, a1, a2, a3, aa + kk * 32);
        ldsm4(c0r, c1r, c2r, c3r, aa + (kk + 8) * 32);
        #pragma unroll
        for (int nbp = 0; nbp < 4; nbp++) {
            uint32_t b0, b1, b2, b3, d0, d1, d2, d3;
            ldsm4(b0, b1, b2, b3, bb + (nbp * 16 * AP + kk * 16) * 2);
            ldsm4(d0, d1, d2, d3, bb + (nbp * 16 * AP + (kk + 8) * 16) * 2);
            mma_f16(acc0[2 * nbp],     a0, a1, a2, a3, b0, b1);
            mma_f16(acc0[2 * nbp + 1], a0, a1, a2, a3, b2, b3);
            mma_f16(acc1[2 * nbp],     c0r, c1r, c2r, c3r, d0, d1);
            mma_f16(acc1[2 * nbp + 1], c0r, c1r, c2r, c3r, d2, d3);
        }
    }

    // stage D transposed [o_local][token] in fp32
    __syncthreads();
    #pragma unroll
    for (int nb = 0; nb < 8; nb++) {
        int ol = nb * 8 + 2 * t;
        Ts[ol * 136 + wrow + g]           = acc0[nb][0] + acc1[nb][0];
        Ts[(ol + 1) * 136 + wrow + g]     = acc0[nb][1] + acc1[nb][1];
        Ts[ol * 136 + wrow + g + 8]       = acc0[nb][2] + acc1[nb][2];
        Ts[(ol + 1) * 136 + wrow + g + 8] = acc0[nb][3] + acc1[nb][3];
    }
    __syncthreads();

    for (int idx = tid; idx < 2048; idx += 256) {
        int o = idx >> 5, n4 = (idx & 31) * 4;
        int og = o0 + o;
        float bo = bias[og];
        size_t base = ((size_t)b * C_ + og) * N_ + n0 + n4;
        float4 res = *(const float4*)&x[base];
        float4 d   = *(const float4*)&Ts[o * 136 + n4];
        float4 r = make_float4(d.x + bo + res.x, d.y + bo + res.y,
                               d.z + bo + res.z, d.w + bo + res.w);
        *(float4*)&out[base] = r;
    }
}

// ---------------------------------------------------------------------------
// Launch
// ---------------------------------------------------------------------------
extern "C" void kernel_launch(void* const* d_in, const int* in_sizes, int n_in,
                              void* d_out, int out_size)
{
    const float* x        = (const float*)d_in[0];
    const float* gn_scale = (const float*)d_in[1];
    const float* gn_bias  = (const float*)d_in[2];
    const float* w_qkv    = (const float*)d_in[3];
    const float* b_qkv    = (const float*)d_in[4];
    const float* w_out    = (const float*)d_in[5];
    const float* b_out    = (const float*)d_in[6];
    float* out = (float*)d_out;

    cudaFuncSetAttribute(flash_kernel,
                         cudaFuncAttributeMaxDynamicSharedMemorySize, FL_SMEM);
    cudaFuncSetAttribute(qkv_hgemm_kernel,
                         cudaFuncAttributeMaxDynamicSharedMemorySize, HG_SMEM);
    cudaFuncSetAttribute(proj_hgemm_kernel,
                         cudaFuncAttributeMaxDynamicSharedMemorySize, HG_SMEM);

    wconv_kernel<<<256, 256>>>(w_qkv, w_out);
    gn_part_kernel<<<512, 256>>>(x);
    gn_fin_kernel<<<64, 32>>>(gn_scale, gn_bias);
    xn_half_kernel<<<dim3(N_ / 256, C_ / 64, B_), 256>>>(x);
    qkv_hgemm_kernel<<<dim3(N_ / 128, 12, B_), 256, HG_SMEM>>>(b_qkv);
    flash_kernel<<<dim3(N_ / 128, B_), 256, FL_SMEM>>>();
    proj_hgemm_kernel<<<dim3(N_ / 128, 4, B_), 256, HG_SMEM>>>(b_out, x, out);
}